// round 16
// baseline (speedup 1.0000x reference)
#include <cuda_runtime.h>
#include <cuda_fp16.h>
#include <math.h>
#include <stdint.h>

#define NROWS 65536
#define PER   64
#define NBLK  1024
#define NC    36
#define NCP   40
#define OBJ   192
#define EMB   200
#define POSD  128
#define HID   1024
#define KEFF  355
#define KP    384
#define EPS   1e-5f

#define WSCALE    64.f
#define INV_WSCALE 0.015625f

// GEMM1: 128x256 tile, K-chunks of 64, 512 threads, 1 CTA/SM, bulk-async loads
#define BM 128
#define BN 256
#define BKC 64
#define NCH (KP / BKC)            // 6
#define AH_OFF 0
#define AL_OFF 16384
#define WH_OFF 32768
#define WL_OFF 65536
#define STAGE_BYTES 98304

// epilogue overlay (reuses stage space after mainloop)
#define GSTRH 264
#define GH_WORDS (128 * GSTRH / 2)
#define W2_TILE_BYTES (NCP * GSTRH * 2)
#define W2H_OFF (2 * GH_WORDS * 4)
#define W2L_OFF (W2H_OFF + W2_TILE_BYTES)
#define SB1_OFF (2 * STAGE_BYTES)
#define MBAR_OFF (SB1_OFF + 1024)
#define SMEM_GEMM (MBAR_OFF + 64)

#define NJT (HID / BN)            // 4 partials
#define WSEG 48                   // KP/8 segments per j
#define W1BLKS (HID * WSEG / 256) // 192

__device__ __forceinline__ uint32_t sw128(uint32_t o) { return o ^ ((o >> 3) & 0x70); }

// ---------------- device scratch ----------------
// chunk-major, pre-swizzled: A[(c*NROWS + row)*64 + k], W[(c*HID + j)*64 + k]
__device__ __half d_Ah[(size_t)NROWS * KP];
__device__ __half d_Al[(size_t)NROWS * KP];
__device__ __half d_WhT[(size_t)HID * KP];
__device__ __half d_WlT[(size_t)HID * KP];
__device__ __half d_W2h[(size_t)NCP * HID];
__device__ __half d_W2l[(size_t)NCP * HID];
__device__ float  d_b1[HID];
__device__ float  d_a[HID];
__device__ float  d_PW[4 * POSD];
__device__ float  d_pb[POSD];
__device__ float  d_part[(size_t)NJT * NC * NROWS];

// ---------------- launch 1: fused prep ----------------
__global__ void k_prep(const float* __restrict__ bn1k_g, const float* __restrict__ bn1k_b,
                       const float* __restrict__ bn1k_m, const float* __restrict__ bn1k_v,
                       const float* __restrict__ dec1_b,
                       const float* __restrict__ g4, const float* __restrict__ b4,
                       const float* __restrict__ m4, const float* __restrict__ v4,
                       const float* __restrict__ pos_W, const float* __restrict__ pos_b) {
    int b = blockIdx.x, t = threadIdx.x;
    if (b < 4) {
        int j = b * 256 + t;
        float a = bn1k_g[j] * rsqrtf(bn1k_v[j] + EPS);
        float c = bn1k_b[j] - bn1k_m[j] * a;
        d_a[j]  = a;
        d_b1[j] = dec1_b[j] * a + c;
    } else if (t < POSD) {
        int j = t;
        float s[4], tt[4];
#pragma unroll
        for (int k = 0; k < 4; k++) {
            s[k]  = g4[k] * rsqrtf(v4[k] + EPS);
            tt[k] = b4[k] - m4[k] * s[k];
        }
        float pb = pos_b[j];
#pragma unroll
        for (int k = 0; k < 4; k++) {
            float w = pos_W[k * POSD + j];
            d_PW[k * POSD + j] = s[k] * w;
            pb += tt[k] * w;
        }
        d_pb[j] = pb;
    }
}

// ---------------- launch 2: fold W + dec2_W^T, 16B swizzled stores ----------------
__global__ void k_weights(const float* __restrict__ dec1_W,
                          const float* __restrict__ obj_embed_W,
                          const float* __restrict__ dec2_W) {
    int b = blockIdx.x, t = threadIdx.x;
    if (b < W1BLKS) {
        int idx = b * 256 + t;          // over j*WSEG + seg
        int j = idx / WSEG, seg = idx % WSEG;
        float aj = d_a[j] * WSCALE;
        __half hh[8], hl[8];
#pragma unroll
        for (int i = 0; i < 8; i++) {
            int k = seg * 8 + i;
            float v;
            if (k < OBJ) {
                v = dec1_W[(size_t)k * HID + j];
            } else if (k < OBJ + 35) {
                int e = k - OBJ;
                const float* er = obj_embed_W + e * EMB;
                float s = 0.f;
#pragma unroll 8
                for (int kk = 0; kk < EMB; kk++)
                    s += er[kk] * dec1_W[(size_t)(OBJ + kk) * HID + j];
                v = s;
            } else if (k < KEFF) {
                v = dec1_W[(size_t)(OBJ + EMB + (k - (OBJ + 35))) * HID + j];
            } else {
                v = 0.f;
            }
            v *= aj;
            hh[i] = __float2half_rn(v);
            hl[i] = __float2half_rn(v - __half2float(hh[i]));
        }
        int c = seg >> 3, kl = (seg & 7) * 8, jl = j & 255;
        size_t base = ((size_t)c * HID + (j & ~255)) * 128;
        uint32_t loff = sw128((uint32_t)(jl * 128 + kl * 2));
        *(uint4*)((char*)d_WhT + base + loff) = *(uint4*)hh;
        *(uint4*)((char*)d_WlT + base + loff) = *(uint4*)hl;
    } else {
        int idx = (b - W1BLKS) * 256 + t;
        if (idx >= NCP * HID) return;
        int c = idx / HID, j = idx % HID;
        float v = (c < NC) ? dec2_W[(size_t)j * NC + c] * WSCALE : 0.f;
        __half h = __float2half_rn(v);
        d_W2h[idx] = h;
        d_W2l[idx] = __float2half_rn(v - __half2float(h));
    }
}

// ---------------- launch 3: build fused A, 16B swizzled stores (8 rows/block) ----------------
__global__ __launch_bounds__(384) void k_buildA(const float* __restrict__ features,
                                                const float* __restrict__ distribution,
                                                const float* __restrict__ boxes) {
    int t   = threadIdx.x;            // 0..383
    int rl8 = t / WSEG;               // 0..7 row within block
    int seg = t % WSEG;               // 0..47
    int r   = blockIdx.x * 8 + rl8;

    float x1 = boxes[(size_t)r * 5 + 1], y1 = boxes[(size_t)r * 5 + 2];
    float x2 = boxes[(size_t)r * 5 + 3], y2 = boxes[(size_t)r * 5 + 4];
    float w = x2 - x1 + 1.f, h = y2 - y1 + 1.f;
    float cx = x1 + 0.5f * w, cy = y1 + 0.5f * h;

    __half hh[8], hl[8];
#pragma unroll
    for (int i = 0; i < 8; i++) {
        int col = seg * 8 + i;
        float v;
        if (col < OBJ)      v = features[(size_t)r * OBJ + col];
        else if (col < 227) v = distribution[(size_t)r * 35 + (col - OBJ)];
        else if (col < KEFF) {
            int p = col - 227;
            float pv = d_pb[p] + cx * d_PW[p] + cy * d_PW[POSD + p]
                              + w  * d_PW[2 * POSD + p] + h * d_PW[3 * POSD + p];
            v = fmaxf(pv, 0.f);
        } else v = 0.f;
        hh[i] = __float2half_rn(v);
        hl[i] = __float2half_rn(v - __half2float(hh[i]));
    }
    int c = seg >> 3, kl = (seg & 7) * 8, lr = r & 127;
    size_t base = ((size_t)c * NROWS + (r & ~127)) * 128;
    uint32_t loff = sw128((uint32_t)(lr * 128 + kl * 2));
    *(uint4*)((char*)d_Ah + base + loff) = *(uint4*)hh;
    *(uint4*)((char*)d_Al + base + loff) = *(uint4*)hl;
}

// ---------------- launch 4: GEMM1 (bulk-async, depth-2) + tensor logits epilogue ----------------
__device__ __forceinline__ void mma_f16(float& c0, float& c1, float& c2, float& c3,
                                        uint32_t a0, uint32_t a1, uint32_t a2, uint32_t a3,
                                        uint32_t b0, uint32_t b1) {
    asm volatile(
        "mma.sync.aligned.m16n8k16.row.col.f32.f16.f16.f32 "
        "{%0,%1,%2,%3}, {%4,%5,%6,%7}, {%8,%9}, {%0,%1,%2,%3};"
        : "+f"(c0), "+f"(c1), "+f"(c2), "+f"(c3)
        : "r"(a0), "r"(a1), "r"(a2), "r"(a3), "r"(b0), "r"(b1));
}
__device__ __forceinline__ void cp16(uint32_t dst, const void* src) {
    asm volatile("cp.async.cg.shared.global [%0], [%1], 16;" :: "r"(dst), "l"(src));
}
__device__ __forceinline__ void bulk_ld(uint32_t dst, const void* src, uint32_t bytes,
                                        uint32_t mbar) {
    asm volatile(
        "cp.async.bulk.shared::cta.global.mbarrier::complete_tx::bytes [%0], [%1], %2, [%3];"
        :: "r"(dst), "l"(src), "r"(bytes), "r"(mbar) : "memory");
}
__device__ __forceinline__ void mbar_init(uint32_t mbar, uint32_t count) {
    asm volatile("mbarrier.init.shared.b64 [%0], %1;" :: "r"(mbar), "r"(count) : "memory");
}
__device__ __forceinline__ void mbar_expect(uint32_t mbar, uint32_t bytes) {
    asm volatile("mbarrier.arrive.expect_tx.shared.b64 _, [%0], %1;"
                 :: "r"(mbar), "r"(bytes) : "memory");
}
__device__ __forceinline__ void mbar_wait(uint32_t mbar, uint32_t parity) {
    asm volatile(
        "{\n\t.reg .pred P;\n\t"
        "W_%=:\n\t"
        "mbarrier.try_wait.parity.shared.b64 P, [%0], %1;\n\t"
        "@!P bra W_%=;\n\t}"
        :: "r"(mbar), "r"(parity) : "memory");
}
__device__ __forceinline__ void ldm4(uint32_t& r0, uint32_t& r1, uint32_t& r2, uint32_t& r3,
                                     uint32_t a) {
    asm volatile("ldmatrix.sync.aligned.m8n8.x4.shared.b16 {%0,%1,%2,%3}, [%4];"
                 : "=r"(r0), "=r"(r1), "=r"(r2), "=r"(r3) : "r"(a));
}
__device__ __forceinline__ uint32_t pack2(float x, float y) {
    __half2 h2 = __halves2half2(__float2half_rn(x), __float2half_rn(y));
    return *(uint32_t*)&h2;
}

__global__ __launch_bounds__(512, 1) void k_gemm1() {
    extern __shared__ __half sh[];
    uint32_t su = (uint32_t)__cvta_generic_to_shared(sh);

    int t    = threadIdx.x;
    int lane = t & 31;
    int warp = t >> 5;
    int qr   = lane >> 2;
    int qc   = lane & 3;
    int wm   = (warp >> 3) * 64;
    int wn   = (warp & 7) * 32;
    int i0   = blockIdx.y * BM;
    int j0   = blockIdx.x * BN;

    int aRow  = wm + (lane & 15);
    int aKoff = (lane >> 4) << 3;
    int bRow  = wn + ((lane >> 4) << 3) + (lane & 7);
    int bKoff = lane & 8;

    uint32_t mb = su + MBAR_OFF;

    float acc[4][4][4];
#pragma unroll
    for (int mi = 0; mi < 4; mi++)
#pragma unroll
        for (int ni = 0; ni < 4; ni++)
#pragma unroll
            for (int q = 0; q < 4; q++) acc[mi][ni][q] = 0.f;

    auto issue_chunk = [&](int buf, int c) {
        uint32_t base = su + buf * STAGE_BYTES;
        uint32_t mbar = mb + 8 * buf;
        mbar_expect(mbar, STAGE_BYTES);
        size_t aoff = ((size_t)c * NROWS + i0) * 64;
        size_t woff = ((size_t)c * HID + j0) * 64;
        bulk_ld(base + AH_OFF, d_Ah  + aoff, 16384, mbar);
        bulk_ld(base + AL_OFF, d_Al  + aoff, 16384, mbar);
        bulk_ld(base + WH_OFF, d_WhT + woff, 32768, mbar);
        bulk_ld(base + WL_OFF, d_WlT + woff, 32768, mbar);
    };

    if (t == 0) { mbar_init(mb, 1); mbar_init(mb + 8, 1); }
    if (t < 256) ((float*)((char*)sh + SB1_OFF))[t] = d_b1[j0 + t];
    __syncthreads();
    if (t == 0) { issue_chunk(0, 0); issue_chunk(1, 1); }   // depth-2 prologue

    int ph0 = 0, ph1 = 0;
    for (int c = 0; c < NCH; c++) {
        int buf = c & 1;
        if (buf == 0) { mbar_wait(mb, ph0);     ph0 ^= 1; }
        else          { mbar_wait(mb + 8, ph1); ph1 ^= 1; }

        uint32_t base = su + buf * STAGE_BYTES;
        bool last = (c == NCH - 1);

#pragma unroll
        for (int kk = 0; kk < 4; kk++) {
            if (kk == 3 && last) break;
            int kw2 = kk * 16;
            uint32_t ah[4][4], al[4][4];
#pragma unroll
            for (int mi = 0; mi < 4; mi++) {
                uint32_t o = sw128((uint32_t)((aRow + mi * 16) * 128 + (kw2 + aKoff) * 2));
                ldm4(ah[mi][0], ah[mi][1], ah[mi][2], ah[mi][3], base + AH_OFF + o);
                ldm4(al[mi][0], al[mi][1], al[mi][2], al[mi][3], base + AL_OFF + o);
            }
            uint32_t bh[4][2], bl[4][2];
#pragma unroll
            for (int p = 0; p < 2; p++) {
                uint32_t o = sw128((uint32_t)((bRow + p * 16) * 128 + (kw2 + bKoff) * 2));
                ldm4(bh[2 * p][0], bh[2 * p][1], bh[2 * p + 1][0], bh[2 * p + 1][1],
                     base + WH_OFF + o);
                ldm4(bl[2 * p][0], bl[2 * p][1], bl[2 * p + 1][0], bl[2 * p + 1][1],
                     base + WL_OFF + o);
            }
#pragma unroll
            for (int mi = 0; mi < 4; mi++)
#pragma unroll
                for (int ni = 0; ni < 4; ni++)
                    mma_f16(acc[mi][ni][0], acc[mi][ni][1], acc[mi][ni][2], acc[mi][ni][3],
                            ah[mi][0], ah[mi][1], ah[mi][2], ah[mi][3],
                            bh[ni][0], bh[ni][1]);
#pragma unroll
            for (int mi = 0; mi < 4; mi++)
#pragma unroll
                for (int ni = 0; ni < 4; ni++)
                    mma_f16(acc[mi][ni][0], acc[mi][ni][1], acc[mi][ni][2], acc[mi][ni][3],
                            al[mi][0], al[mi][1], al[mi][2], al[mi][3],
                            bh[ni][0], bh[ni][1]);
#pragma unroll
            for (int mi = 0; mi < 4; mi++)
#pragma unroll
                for (int ni = 0; ni < 4; ni++)
                    mma_f16(acc[mi][ni][0], acc[mi][ni][1], acc[mi][ni][2], acc[mi][ni][3],
                            ah[mi][0], ah[mi][1], ah[mi][2], ah[mi][3],
                            bl[ni][0], bl[ni][1]);
        }
        __syncthreads();                           // all warps done with buf
        if (c + 2 < NCH && t == 0) issue_chunk(buf, c + 2);
    }

    // ---- load W2 slices into overlay ----
    for (int i = t; i < NCP * 32; i += 512) {
        int c = i >> 5, ch = i & 31;
        uint32_t dsto = (uint32_t)(c * GSTRH * 2 + ch * 16);
        size_t src = (size_t)c * HID + j0 + ch * 8;
        cp16(su + W2H_OFF + dsto, d_W2h + src);
        cp16(su + W2L_OFF + dsto, d_W2l + src);
    }
    asm volatile("cp.async.commit_group;");

    // ---- epilogue A: acc -> g (fp16 hi/lo) in SMEM overlay ----
    uint32_t* GHW = (uint32_t*)sh;
    uint32_t* GLW = GHW + GH_WORDS;
    const float* sb1 = (const float*)((char*)sh + SB1_OFF);

#pragma unroll
    for (int mi = 0; mi < 4; mi++) {
        int rl = wm + mi * 16 + qr;
#pragma unroll
        for (int ni = 0; ni < 4; ni++) {
            int jl = wn + ni * 8 + 2 * qc;
            float bj0 = sb1[jl], bj1 = sb1[jl + 1];
            float g00 = fmaxf(fmaf(acc[mi][ni][0], INV_WSCALE, bj0), 0.f);
            float g01 = fmaxf(fmaf(acc[mi][ni][1], INV_WSCALE, bj1), 0.f);
            float g10 = fmaxf(fmaf(acc[mi][ni][2], INV_WSCALE, bj0), 0.f);
            float g11 = fmaxf(fmaf(acc[mi][ni][3], INV_WSCALE, bj1), 0.f);
            uint32_t h0 = pack2(g00, g01), h1 = pack2(g10, g11);
            float r00 = g00 - __half2float(__low2half(*(__half2*)&h0));
            float r01 = g01 - __half2float(__high2half(*(__half2*)&h0));
            float r10 = g10 - __half2float(__low2half(*(__half2*)&h1));
            float r11 = g11 - __half2float(__high2half(*(__half2*)&h1));
            int w0 = rl * (GSTRH / 2) + (jl >> 1);
            int w1 = (rl + 8) * (GSTRH / 2) + (jl >> 1);
            GHW[w0] = h0;            GHW[w1] = h1;
            GLW[w0] = pack2(r00, r01);
            GLW[w1] = pack2(r10, r11);
        }
    }
    asm volatile("cp.async.wait_group 0;");
    __syncthreads();

    // ---- epilogue B: logits partial via mma (K=256 per CTA) ----
    {
        const uint32_t* W2H = (const uint32_t*)((char*)sh + W2H_OFF);
        const uint32_t* W2L = (const uint32_t*)((char*)sh + W2L_OFF);
        int wq    = warp & 7;
        int nbase = (warp >> 3) * 3;
        float a2[3][4];
#pragma unroll
        for (int nn = 0; nn < 3; nn++)
#pragma unroll
            for (int q = 0; q < 4; q++) a2[nn][q] = 0.f;

#pragma unroll
        for (int kt = 0; kt < 16; kt++) {
            int w0 = (16 * wq + qr) * (GSTRH / 2) + kt * 8 + qc;
            uint32_t ah0 = GHW[w0], ah1 = GHW[w0 + 8 * (GSTRH / 2)];
            uint32_t ah2 = GHW[w0 + 4], ah3 = GHW[w0 + 8 * (GSTRH / 2) + 4];
            uint32_t al0 = GLW[w0], al1 = GLW[w0 + 8 * (GSTRH / 2)];
            uint32_t al2 = GLW[w0 + 4], al3 = GLW[w0 + 8 * (GSTRH / 2) + 4];
#pragma unroll
            for (int nn = 0; nn < 3; nn++) {
                int ni = nbase + nn;
                if (ni < 5) {
                    int v0 = (8 * ni + qr) * (GSTRH / 2) + kt * 8 + qc;
                    uint32_t bh0 = W2H[v0], bh1 = W2H[v0 + 4];
                    uint32_t bl0 = W2L[v0], bl1 = W2L[v0 + 4];
                    mma_f16(a2[nn][0], a2[nn][1], a2[nn][2], a2[nn][3],
                            ah0, ah1, ah2, ah3, bh0, bh1);
                    mma_f16(a2[nn][0], a2[nn][1], a2[nn][2], a2[nn][3],
                            al0, al1, al2, al3, bh0, bh1);
                    mma_f16(a2[nn][0], a2[nn][1], a2[nn][2], a2[nn][3],
                            ah0, ah1, ah2, ah3, bl0, bl1);
                }
            }
        }

        size_t r0 = (size_t)(i0 + 16 * wq + qr);
#pragma unroll
        for (int nn = 0; nn < 3; nn++) {
            int ni = nbase + nn;
            if (ni < 5) {
                int c = 8 * ni + 2 * qc;
                if (c < NC) {
                    float* p = &d_part[((size_t)blockIdx.x * NC + c) * NROWS];
                    p[r0]     = a2[nn][0] * INV_WSCALE;
                    p[r0 + 8] = a2[nn][2] * INV_WSCALE;
                }
                if (c + 1 < NC) {
                    float* p = &d_part[((size_t)blockIdx.x * NC + c + 1) * NROWS];
                    p[r0]     = a2[nn][1] * INV_WSCALE;
                    p[r0 + 8] = a2[nn][3] * INV_WSCALE;
                }
            }
        }
    }
}

// ---------------- launch 5: reduce partials + softmax + pred + human argmax ----------------
__global__ __launch_bounds__(256) void k_pass2(const float* __restrict__ dec2_b,
                                               float* __restrict__ out) {
    __shared__ float sv[256];
    __shared__ int   si[256];
    int t = threadIdx.x;
    int r = blockIdx.x * 256 + t;
    float acc[NC];
#pragma unroll
    for (int c = 0; c < NC; c++) acc[c] = dec2_b[c];

#pragma unroll
    for (int p = 0; p < NJT; p++)
#pragma unroll
        for (int c = 0; c < NC; c++)
            acc[c] += d_part[((size_t)p * NC + c) * NROWS + r];

    float m = acc[1];
#pragma unroll
    for (int c = 2; c < NC; c++) m = fmaxf(m, acc[c]);
    float e[35], s = 0.f;
#pragma unroll
    for (int i = 0; i < 35; i++) { e[i] = expf(acc[1 + i] - m); s += e[i]; }
    float inv = 1.f / s;
#pragma unroll
    for (int i = 0; i < 35; i++) out[(size_t)r * 35 + i] = e[i] * inv;

    float best = e[1]; int bi = 1;
#pragma unroll
    for (int i = 2; i < 35; i++) if (e[i] > best) { best = e[i]; bi = i; }
    float score = best * inv;
    float label = (float)(bi + 1);
    float d0 = e[0] * inv;

    sv[t] = d0;
    si[t] = t & 63;
    __syncthreads();
#pragma unroll
    for (int off = 32; off > 0; off >>= 1) {
        if ((t & 63) < off) {
            float v2 = sv[t + off]; int i2 = si[t + off];
            if (v2 > sv[t] || (v2 == sv[t] && i2 < si[t])) { sv[t] = v2; si[t] = i2; }
        }
        __syncthreads();
    }
    int base = t & ~63;
    int win  = si[base];
    if ((t & 63) == win) { score = d0; label = 1.0f; }
    out[(size_t)NROWS * 35 + r]         = score;
    out[(size_t)NROWS * 35 + NROWS + r] = label;
    if ((t & 63) == 0)
        out[(size_t)NROWS * 35 + 2 * NROWS + (r >> 6)] = (float)(blockIdx.x * 256 + base + win);
}

// ---------------- launcher ----------------
extern "C" void kernel_launch(void* const* d_in, const int* in_sizes, int n_in,
                              void* d_out, int out_size) {
    const float* distribution = (const float*)d_in[0];
    const float* features     = (const float*)d_in[1];
    const float* boxes        = (const float*)d_in[2];
    const float* obj_embed_W  = (const float*)d_in[3];
    const float* bn4_g        = (const float*)d_in[4];
    const float* bn4_b        = (const float*)d_in[5];
    const float* bn4_m        = (const float*)d_in[6];
    const float* bn4_v        = (const float*)d_in[7];
    const float* pos_W        = (const float*)d_in[8];
    const float* pos_b        = (const float*)d_in[9];
    const float* dec1_W       = (const float*)d_in[10];
    const float* dec1_b       = (const float*)d_in[11];
    const float* bn1k_g       = (const float*)d_in[12];
    const float* bn1k_b       = (const float*)d_in[13];
    const float* bn1k_m       = (const float*)d_in[14];
    const float* bn1k_v       = (const float*)d_in[15];
    const float* dec2_W       = (const float*)d_in[16];
    const float* dec2_b       = (const float*)d_in[17];
    float* out = (float*)d_out;

    k_prep<<<5, 256>>>(bn1k_g, bn1k_b, bn1k_m, bn1k_v, dec1_b,
                       bn4_g, bn4_b, bn4_m, bn4_v, pos_W, pos_b);
    k_weights<<<W1BLKS + (NCP * HID + 255) / 256, 256>>>(dec1_W, obj_embed_W, dec2_W);
    k_buildA<<<NROWS / 8, 384>>>(features, distribution, boxes);

    cudaFuncSetAttribute(k_gemm1, cudaFuncAttributeMaxDynamicSharedMemorySize, SMEM_GEMM);
    k_gemm1<<<dim3(HID / BN, NROWS / BM), 512, SMEM_GEMM>>>();

    k_pass2<<<NROWS / 256, 256>>>(dec2_b, out);
}

// round 17
// speedup vs baseline: 1.1639x; 1.1639x over previous
#include <cuda_runtime.h>
#include <cuda_fp16.h>
#include <math.h>
#include <stdint.h>

#define NROWS 65536
#define PER   64
#define NBLK  1024
#define NC    36
#define NCP   40
#define OBJ   192
#define EMB   200
#define POSD  128
#define HID   1024
#define KEFF  355
#define KP    384
#define EPS   1e-5f

#define WSCALE    64.f
#define INV_WSCALE 0.015625f

// GEMM1: 128x256 tile, K-chunks of 64, 512 threads, 1 CTA/SM, bulk-async loads
#define BM 128
#define BN 256
#define BKC 64
#define NCH (KP / BKC)            // 6
#define AH_OFF 0
#define AL_OFF 16384
#define WH_OFF 32768
#define WL_OFF 65536
#define STAGE_BYTES 98304

// epilogue overlay (reuses stage space after mainloop)
#define GSTRH 264
#define GH_WORDS (128 * GSTRH / 2)
#define W2_TILE_BYTES (NCP * GSTRH * 2)
#define W2H_OFF (2 * GH_WORDS * 4)
#define W2L_OFF (W2H_OFF + W2_TILE_BYTES)
#define SB1_OFF (2 * STAGE_BYTES)
#define MBAR_OFF (SB1_OFF + 1024)
#define SMEM_GEMM (MBAR_OFF + 64)

#define NJT (HID / BN)            // 4 partials
#define W1BLKS (HID * KP / 256)   // 1536

__device__ __forceinline__ uint32_t sw128(uint32_t o) { return o ^ ((o >> 3) & 0x70); }

// ---------------- device scratch ----------------
// chunk-major, pre-swizzled: A[(c*NROWS + row)*64 + k], W[(c*HID + j)*64 + k]
__device__ __half d_Ah[(size_t)NROWS * KP];
__device__ __half d_Al[(size_t)NROWS * KP];
__device__ __half d_WhT[(size_t)HID * KP];
__device__ __half d_WlT[(size_t)HID * KP];
__device__ __half d_W2h[(size_t)NCP * HID];
__device__ __half d_W2l[(size_t)NCP * HID];
__device__ float  d_M1[4][35 * HID];          // embed-fold partials (deterministic)
__device__ float  d_b1[HID];
__device__ float  d_a[HID];
__device__ float  d_PW[4 * POSD];
__device__ float  d_pb[POSD];
__device__ float  d_part[(size_t)NJT * NC * NROWS];

// ---------------- launch 1: fused prep ----------------
__global__ void k_prep(const float* __restrict__ bn1k_g, const float* __restrict__ bn1k_b,
                       const float* __restrict__ bn1k_m, const float* __restrict__ bn1k_v,
                       const float* __restrict__ dec1_b,
                       const float* __restrict__ g4, const float* __restrict__ b4,
                       const float* __restrict__ m4, const float* __restrict__ v4,
                       const float* __restrict__ pos_W, const float* __restrict__ pos_b) {
    int b = blockIdx.x, t = threadIdx.x;
    if (b < 4) {
        int j = b * 256 + t;
        float a = bn1k_g[j] * rsqrtf(bn1k_v[j] + EPS);
        float c = bn1k_b[j] - bn1k_m[j] * a;
        d_a[j]  = a;
        d_b1[j] = dec1_b[j] * a + c;
    } else if (t < POSD) {
        int j = t;
        float s[4], tt[4];
#pragma unroll
        for (int k = 0; k < 4; k++) {
            s[k]  = g4[k] * rsqrtf(v4[k] + EPS);
            tt[k] = b4[k] - m4[k] * s[k];
        }
        float pb = pos_b[j];
#pragma unroll
        for (int k = 0; k < 4; k++) {
            float w = pos_W[k * POSD + j];
            d_PW[k * POSD + j] = s[k] * w;
            pb += tt[k] * w;
        }
        d_pb[j] = pb;
    }
}

// ---------------- launch 1b: embed-fold partials (coalesced over j, k-split) ----------------
__global__ void k_m1(const float* __restrict__ obj_embed_W, const float* __restrict__ dec1_W) {
    int j  = blockIdx.x * 256 + threadIdx.x;   // 4 * 256
    int e  = blockIdx.y;                        // 35
    int kc = blockIdx.z;                        // 4 chunks of 50
    float s = 0.f;
#pragma unroll 10
    for (int k = 0; k < 50; k++) {
        int kk = kc * 50 + k;
        s += obj_embed_W[e * EMB + kk] * dec1_W[(size_t)(OBJ + kk) * HID + j];
    }
    d_M1[kc][e * HID + j] = s;
}

// ---------------- launch 2: fold W + dec2_W^T, scale, split fp16, chunk-major swizzled ----------------
__global__ void k_weights(const float* __restrict__ dec1_W,
                          const float* __restrict__ dec2_W) {
    int b = blockIdx.x, t = threadIdx.x;
    if (b < W1BLKS) {
        int idx = b * 256 + t;
        int j = idx / KP, k = idx % KP;
        float v;
        if (k < OBJ) {
            v = dec1_W[(size_t)k * HID + j];
        } else if (k < OBJ + 35) {
            int ei = (k - OBJ) * HID + j;
            v = ((d_M1[0][ei] + d_M1[1][ei]) + d_M1[2][ei]) + d_M1[3][ei];
        } else if (k < KEFF) {
            v = dec1_W[(size_t)(OBJ + EMB + (k - (OBJ + 35))) * HID + j];
        } else {
            v = 0.f;
        }
        v *= d_a[j] * WSCALE;
        __half h = __float2half_rn(v);
        int c = k >> 6, kl = k & 63, jl = j & 255;
        size_t base = ((size_t)c * HID + (j & ~255)) * 128;
        uint32_t loff = sw128((uint32_t)(jl * 128 + kl * 2));
        *(__half*)((char*)d_WhT + base + loff) = h;
        *(__half*)((char*)d_WlT + base + loff) = __float2half_rn(v - __half2float(h));
    } else {
        int idx = (b - W1BLKS) * 256 + t;
        if (idx >= NCP * HID) return;
        int c = idx / HID, j = idx % HID;
        float v = (c < NC) ? dec2_W[(size_t)j * NC + c] * WSCALE : 0.f;
        __half h = __float2half_rn(v);
        d_W2h[idx] = h;
        d_W2l[idx] = __float2half_rn(v - __half2float(h));
    }
}

// ---------------- launch 3: build fused A, pre-split fp16, chunk-major swizzled ----------------
__global__ void k_buildA(const float* __restrict__ features,
                         const float* __restrict__ distribution,
                         const float* __restrict__ boxes) {
    int r = blockIdx.x;
    int t = threadIdx.x;  // 0..191, cols 2t, 2t+1

    float x1 = boxes[(size_t)r * 5 + 1], y1 = boxes[(size_t)r * 5 + 2];
    float x2 = boxes[(size_t)r * 5 + 3], y2 = boxes[(size_t)r * 5 + 4];
    float w = x2 - x1 + 1.f, h = y2 - y1 + 1.f;
    float cx = x1 + 0.5f * w, cy = y1 + 0.5f * h;

    auto val = [&](int col) -> float {
        if (col < OBJ)  return features[(size_t)r * OBJ + col];
        if (col < 227)  return distribution[(size_t)r * 35 + (col - OBJ)];
        if (col < KEFF) {
            int i = col - 227;
            float p = d_pb[i] + cx * d_PW[i] + cy * d_PW[POSD + i]
                             + w  * d_PW[2 * POSD + i] + h * d_PW[3 * POSD + i];
            return fmaxf(p, 0.f);
        }
        return 0.f;
    };

    float v0 = val(2 * t), v1 = val(2 * t + 1);
    __half h0 = __float2half_rn(v0), h1 = __float2half_rn(v1);
    __half2 hi = __halves2half2(h0, h1);
    __half2 lo = __halves2half2(__float2half_rn(v0 - __half2float(h0)),
                                __float2half_rn(v1 - __half2float(h1)));
    int c  = t >> 5;
    int kl = (2 * t) & 63;
    int lr = r & 127;
    size_t base = ((size_t)c * NROWS + (r & ~127)) * 128;
    uint32_t loff = sw128((uint32_t)(lr * 128 + kl * 2));
    *(__half2*)((char*)d_Ah + base + loff) = hi;
    *(__half2*)((char*)d_Al + base + loff) = lo;
}

// ---------------- launch 4: GEMM1 (bulk-async) + tensor-core logits epilogue ----------------
__device__ __forceinline__ void mma_f16(float& c0, float& c1, float& c2, float& c3,
                                        uint32_t a0, uint32_t a1, uint32_t a2, uint32_t a3,
                                        uint32_t b0, uint32_t b1) {
    asm volatile(
        "mma.sync.aligned.m16n8k16.row.col.f32.f16.f16.f32 "
        "{%0,%1,%2,%3}, {%4,%5,%6,%7}, {%8,%9}, {%0,%1,%2,%3};"
        : "+f"(c0), "+f"(c1), "+f"(c2), "+f"(c3)
        : "r"(a0), "r"(a1), "r"(a2), "r"(a3), "r"(b0), "r"(b1));
}
__device__ __forceinline__ void cp16(uint32_t dst, const void* src) {
    asm volatile("cp.async.cg.shared.global [%0], [%1], 16;" :: "r"(dst), "l"(src));
}
__device__ __forceinline__ void bulk_ld(uint32_t dst, const void* src, uint32_t bytes,
                                        uint32_t mbar) {
    asm volatile(
        "cp.async.bulk.shared::cta.global.mbarrier::complete_tx::bytes [%0], [%1], %2, [%3];"
        :: "r"(dst), "l"(src), "r"(bytes), "r"(mbar) : "memory");
}
__device__ __forceinline__ void mbar_init(uint32_t mbar, uint32_t count) {
    asm volatile("mbarrier.init.shared.b64 [%0], %1;" :: "r"(mbar), "r"(count) : "memory");
}
__device__ __forceinline__ void mbar_expect(uint32_t mbar, uint32_t bytes) {
    asm volatile("mbarrier.arrive.expect_tx.shared.b64 _, [%0], %1;"
                 :: "r"(mbar), "r"(bytes) : "memory");
}
__device__ __forceinline__ void mbar_wait(uint32_t mbar, uint32_t parity) {
    asm volatile(
        "{\n\t.reg .pred P;\n\t"
        "W_%=:\n\t"
        "mbarrier.try_wait.parity.shared.b64 P, [%0], %1;\n\t"
        "@!P bra W_%=;\n\t}"
        :: "r"(mbar), "r"(parity) : "memory");
}
__device__ __forceinline__ void ldm4(uint32_t& r0, uint32_t& r1, uint32_t& r2, uint32_t& r3,
                                     uint32_t a) {
    asm volatile("ldmatrix.sync.aligned.m8n8.x4.shared.b16 {%0,%1,%2,%3}, [%4];"
                 : "=r"(r0), "=r"(r1), "=r"(r2), "=r"(r3) : "r"(a));
}
__device__ __forceinline__ uint32_t pack2(float x, float y) {
    __half2 h2 = __halves2half2(__float2half_rn(x), __float2half_rn(y));
    return *(uint32_t*)&h2;
}

__global__ __launch_bounds__(512, 1) void k_gemm1() {
    extern __shared__ __half sh[];
    uint32_t su = (uint32_t)__cvta_generic_to_shared(sh);

    int t    = threadIdx.x;
    int lane = t & 31;
    int warp = t >> 5;
    int qr   = lane >> 2;
    int qc   = lane & 3;
    int wm   = (warp >> 3) * 64;
    int wn   = (warp & 7) * 32;
    int i0   = blockIdx.y * BM;
    int j0   = blockIdx.x * BN;

    int aRow  = wm + (lane & 15);
    int aKoff = (lane >> 4) << 3;
    int bRow  = wn + ((lane >> 4) << 3) + (lane & 7);
    int bKoff = lane & 8;

    uint32_t mb = su + MBAR_OFF;

    float acc[4][4][4];
#pragma unroll
    for (int mi = 0; mi < 4; mi++)
#pragma unroll
        for (int ni = 0; ni < 4; ni++)
#pragma unroll
            for (int q = 0; q < 4; q++) acc[mi][ni][q] = 0.f;

    auto issue_chunk = [&](int buf, int c) {
        uint32_t base = su + buf * STAGE_BYTES;
        uint32_t mbar = mb + 8 * buf;
        mbar_expect(mbar, STAGE_BYTES);
        size_t aoff = ((size_t)c * NROWS + i0) * 64;
        size_t woff = ((size_t)c * HID + j0) * 64;
        bulk_ld(base + AH_OFF, d_Ah  + aoff, 16384, mbar);
        bulk_ld(base + AL_OFF, d_Al  + aoff, 16384, mbar);
        bulk_ld(base + WH_OFF, d_WhT + woff, 32768, mbar);
        bulk_ld(base + WL_OFF, d_WlT + woff, 32768, mbar);
    };

    if (t == 0) { mbar_init(mb, 1); mbar_init(mb + 8, 1); }
    if (t < 256) ((float*)((char*)sh + SB1_OFF))[t] = d_b1[j0 + t];
    __syncthreads();
    if (t == 0) issue_chunk(0, 0);

    int ph0 = 0, ph1 = 0;
    for (int c = 0; c < NCH; c++) {
        int buf = c & 1;
        if (buf == 0) { mbar_wait(mb, ph0);     ph0 ^= 1; }
        else          { mbar_wait(mb + 8, ph1); ph1 ^= 1; }
        __syncthreads();                       // all warps done with buf^1's previous chunk
        if (c + 1 < NCH && t == 0) issue_chunk(buf ^ 1, c + 1);

        uint32_t base = su + buf * STAGE_BYTES;
        bool last = (c == NCH - 1);

#pragma unroll
        for (int kk = 0; kk < 4; kk++) {
            if (kk == 3 && last) break;        // cols 368..383 zero padding
            int kw2 = kk * 16;
            uint32_t ah[4][4], al[4][4];
#pragma unroll
            for (int mi = 0; mi < 4; mi++) {
                uint32_t o = sw128((uint32_t)((aRow + mi * 16) * 128 + (kw2 + aKoff) * 2));
                ldm4(ah[mi][0], ah[mi][1], ah[mi][2], ah[mi][3], base + AH_OFF + o);
                ldm4(al[mi][0], al[mi][1], al[mi][2], al[mi][3], base + AL_OFF + o);
            }
            uint32_t bh[4][2], bl[4][2];
#pragma unroll
            for (int p = 0; p < 2; p++) {
                uint32_t o = sw128((uint32_t)((bRow + p * 16) * 128 + (kw2 + bKoff) * 2));
                ldm4(bh[2 * p][0], bh[2 * p][1], bh[2 * p + 1][0], bh[2 * p + 1][1],
                     base + WH_OFF + o);
                ldm4(bl[2 * p][0], bl[2 * p][1], bl[2 * p + 1][0], bl[2 * p + 1][1],
                     base + WL_OFF + o);
            }
#pragma unroll
            for (int mi = 0; mi < 4; mi++)
#pragma unroll
                for (int ni = 0; ni < 4; ni++)
                    mma_f16(acc[mi][ni][0], acc[mi][ni][1], acc[mi][ni][2], acc[mi][ni][3],
                            ah[mi][0], ah[mi][1], ah[mi][2], ah[mi][3],
                            bh[ni][0], bh[ni][1]);
#pragma unroll
            for (int mi = 0; mi < 4; mi++)
#pragma unroll
                for (int ni = 0; ni < 4; ni++)
                    mma_f16(acc[mi][ni][0], acc[mi][ni][1], acc[mi][ni][2], acc[mi][ni][3],
                            al[mi][0], al[mi][1], al[mi][2], al[mi][3],
                            bh[ni][0], bh[ni][1]);
#pragma unroll
            for (int mi = 0; mi < 4; mi++)
#pragma unroll
                for (int ni = 0; ni < 4; ni++)
                    mma_f16(acc[mi][ni][0], acc[mi][ni][1], acc[mi][ni][2], acc[mi][ni][3],
                            ah[mi][0], ah[mi][1], ah[mi][2], ah[mi][3],
                            bl[ni][0], bl[ni][1]);
        }
    }
    __syncthreads();   // mainloop reads done before overlay reuse

    // ---- load W2 slices into overlay ----
    for (int i = t; i < NCP * 32; i += 512) {
        int c = i >> 5, ch = i & 31;
        uint32_t dsto = (uint32_t)(c * GSTRH * 2 + ch * 16);
        size_t src = (size_t)c * HID + j0 + ch * 8;
        cp16(su + W2H_OFF + dsto, d_W2h + src);
        cp16(su + W2L_OFF + dsto, d_W2l + src);
    }
    asm volatile("cp.async.commit_group;");

    // ---- epilogue A: acc -> g (fp16 hi/lo) in SMEM overlay ----
    uint32_t* GHW = (uint32_t*)sh;
    uint32_t* GLW = GHW + GH_WORDS;
    const float* sb1 = (const float*)((char*)sh + SB1_OFF);

#pragma unroll
    for (int mi = 0; mi < 4; mi++) {
        int rl = wm + mi * 16 + qr;
#pragma unroll
        for (int ni = 0; ni < 4; ni++) {
            int jl = wn + ni * 8 + 2 * qc;
            float bj0 = sb1[jl], bj1 = sb1[jl + 1];
            float g00 = fmaxf(fmaf(acc[mi][ni][0], INV_WSCALE, bj0), 0.f);
            float g01 = fmaxf(fmaf(acc[mi][ni][1], INV_WSCALE, bj1), 0.f);
            float g10 = fmaxf(fmaf(acc[mi][ni][2], INV_WSCALE, bj0), 0.f);
            float g11 = fmaxf(fmaf(acc[mi][ni][3], INV_WSCALE, bj1), 0.f);
            uint32_t h0 = pack2(g00, g01), h1 = pack2(g10, g11);
            float r00 = g00 - __half2float(__low2half(*(__half2*)&h0));
            float r01 = g01 - __half2float(__high2half(*(__half2*)&h0));
            float r10 = g10 - __half2float(__low2half(*(__half2*)&h1));
            float r11 = g11 - __half2float(__high2half(*(__half2*)&h1));
            int w0 = rl * (GSTRH / 2) + (jl >> 1);
            int w1 = (rl + 8) * (GSTRH / 2) + (jl >> 1);
            GHW[w0] = h0;            GHW[w1] = h1;
            GLW[w0] = pack2(r00, r01);
            GLW[w1] = pack2(r10, r11);
        }
    }
    asm volatile("cp.async.wait_group 0;");
    __syncthreads();

    // ---- epilogue B: logits partial via mma (K=256 per CTA) ----
    {
        const uint32_t* W2H = (const uint32_t*)((char*)sh + W2H_OFF);
        const uint32_t* W2L = (const uint32_t*)((char*)sh + W2L_OFF);
        int wq    = warp & 7;
        int nbase = (warp >> 3) * 3;
        float a2[3][4];
#pragma unroll
        for (int nn = 0; nn < 3; nn++)
#pragma unroll
            for (int q = 0; q < 4; q++) a2[nn][q] = 0.f;

#pragma unroll
        for (int kt = 0; kt < 16; kt++) {
            int w0 = (16 * wq + qr) * (GSTRH / 2) + kt * 8 + qc;
            uint32_t ah0 = GHW[w0], ah1 = GHW[w0 + 8 * (GSTRH / 2)];
            uint32_t ah2 = GHW[w0 + 4], ah3 = GHW[w0 + 8 * (GSTRH / 2) + 4];
            uint32_t al0 = GLW[w0], al1 = GLW[w0 + 8 * (GSTRH / 2)];
            uint32_t al2 = GLW[w0 + 4], al3 = GLW[w0 + 8 * (GSTRH / 2) + 4];
#pragma unroll
            for (int nn = 0; nn < 3; nn++) {
                int ni = nbase + nn;
                if (ni < 5) {
                    int v0 = (8 * ni + qr) * (GSTRH / 2) + kt * 8 + qc;
                    uint32_t bh0 = W2H[v0], bh1 = W2H[v0 + 4];
                    uint32_t bl0 = W2L[v0], bl1 = W2L[v0 + 4];
                    mma_f16(a2[nn][0], a2[nn][1], a2[nn][2], a2[nn][3],
                            ah0, ah1, ah2, ah3, bh0, bh1);
                    mma_f16(a2[nn][0], a2[nn][1], a2[nn][2], a2[nn][3],
                            al0, al1, al2, al3, bh0, bh1);
                    mma_f16(a2[nn][0], a2[nn][1], a2[nn][2], a2[nn][3],
                            ah0, ah1, ah2, ah3, bl0, bl1);
                }
            }
        }

        size_t r0 = (size_t)(i0 + 16 * wq + qr);
#pragma unroll
        for (int nn = 0; nn < 3; nn++) {
            int ni = nbase + nn;
            if (ni < 5) {
                int c = 8 * ni + 2 * qc;
                if (c < NC) {
                    float* p = &d_part[((size_t)blockIdx.x * NC + c) * NROWS];
                    p[r0]     = a2[nn][0] * INV_WSCALE;
                    p[r0 + 8] = a2[nn][2] * INV_WSCALE;
                }
                if (c + 1 < NC) {
                    float* p = &d_part[((size_t)blockIdx.x * NC + c + 1) * NROWS];
                    p[r0]     = a2[nn][1] * INV_WSCALE;
                    p[r0 + 8] = a2[nn][3] * INV_WSCALE;
                }
            }
        }
    }
}

// ---------------- launch 5: reduce partials + softmax + pred + human argmax ----------------
__global__ __launch_bounds__(256) void k_pass2(const float* __restrict__ dec2_b,
                                               float* __restrict__ out) {
    __shared__ float sv[256];
    __shared__ int   si[256];
    int t = threadIdx.x;
    int r = blockIdx.x * 256 + t;
    float acc[NC];
#pragma unroll
    for (int c = 0; c < NC; c++) acc[c] = dec2_b[c];

#pragma unroll
    for (int p = 0; p < NJT; p++)
#pragma unroll
        for (int c = 0; c < NC; c++)
            acc[c] += d_part[((size_t)p * NC + c) * NROWS + r];

    float m = acc[1];
#pragma unroll
    for (int c = 2; c < NC; c++) m = fmaxf(m, acc[c]);
    float e[35], s = 0.f;
#pragma unroll
    for (int i = 0; i < 35; i++) { e[i] = expf(acc[1 + i] - m); s += e[i]; }
    float inv = 1.f / s;
#pragma unroll
    for (int i = 0; i < 35; i++) out[(size_t)r * 35 + i] = e[i] * inv;

    float best = e[1]; int bi = 1;
#pragma unroll
    for (int i = 2; i < 35; i++) if (e[i] > best) { best = e[i]; bi = i; }
    float score = best * inv;
    float label = (float)(bi + 1);
    float d0 = e[0] * inv;

    sv[t] = d0;
    si[t] = t & 63;
    __syncthreads();
#pragma unroll
    for (int off = 32; off > 0; off >>= 1) {
        if ((t & 63) < off) {
            float v2 = sv[t + off]; int i2 = si[t + off];
            if (v2 > sv[t] || (v2 == sv[t] && i2 < si[t])) { sv[t] = v2; si[t] = i2; }
        }
        __syncthreads();
    }
    int base = t & ~63;
    int win  = si[base];
    if ((t & 63) == win) { score = d0; label = 1.0f; }
    out[(size_t)NROWS * 35 + r]         = score;
    out[(size_t)NROWS * 35 + NROWS + r] = label;
    if ((t & 63) == 0)
        out[(size_t)NROWS * 35 + 2 * NROWS + (r >> 6)] = (float)(blockIdx.x * 256 + base + win);
}

// ---------------- launcher ----------------
extern "C" void kernel_launch(void* const* d_in, const int* in_sizes, int n_in,
                              void* d_out, int out_size) {
    const float* distribution = (const float*)d_in[0];
    const float* features     = (const float*)d_in[1];
    const float* boxes        = (const float*)d_in[2];
    const float* obj_embed_W  = (const float*)d_in[3];
    const float* bn4_g        = (const float*)d_in[4];
    const float* bn4_b        = (const float*)d_in[5];
    const float* bn4_m        = (const float*)d_in[6];
    const float* bn4_v        = (const float*)d_in[7];
    const float* pos_W        = (const float*)d_in[8];
    const float* pos_b        = (const float*)d_in[9];
    const float* dec1_W       = (const float*)d_in[10];
    const float* dec1_b       = (const float*)d_in[11];
    const float* bn1k_g       = (const float*)d_in[12];
    const float* bn1k_b       = (const float*)d_in[13];
    const float* bn1k_m       = (const float*)d_in[14];
    const float* bn1k_v       = (const float*)d_in[15];
    const float* dec2_W       = (const float*)d_in[16];
    const float* dec2_b       = (const float*)d_in[17];
    float* out = (float*)d_out;

    k_prep<<<5, 256>>>(bn1k_g, bn1k_b, bn1k_m, bn1k_v, dec1_b,
                       bn4_g, bn4_b, bn4_m, bn4_v, pos_W, pos_b);
    k_m1<<<dim3(4, 35, 4), 256>>>(obj_embed_W, dec1_W);
    k_weights<<<W1BLKS + (NCP * HID + 255) / 256, 256>>>(dec1_W, dec2_W);
    k_buildA<<<NROWS, 192>>>(features, distribution, boxes);

    cudaFuncSetAttribute(k_gemm1, cudaFuncAttributeMaxDynamicSharedMemorySize, SMEM_GEMM);
    k_gemm1<<<dim3(HID / BN, NROWS / BM), 512, SMEM_GEMM>>>();

    k_pass2<<<NROWS / 256, 256>>>(dec2_b, out);
}